// round 17
// baseline (speedup 1.0000x reference)
#include <cuda_runtime.h>
#include <cuda_bf16.h>
#include <cuda_fp16.h>
#include <math.h>
#include <stdint.h>

// ---------------- problem constants ----------------
#define NLAYER   8
#define DMODEL   1024
#define NHEAD    16
#define HEADDIM  64
#define DFF      4096
#define VOCAB    4096
#define BATCH    4
#define SEQ      2048
#define MTOK     (BATCH*SEQ)      // 8192 tokens

// ---------------- scratch (device globals; no allocation allowed) ----------------
__device__ float g_x  [MTOK*DMODEL];       // residual stream (fp32)
__device__ float g_qkv[MTOK*3*DMODEL];     // qkv (fp32, attention input)
__device__ __half g_hhi[MTOK*DMODEL];      // activation hi/lo (fp16)
__device__ __half g_hlo[MTOK*DMODEL];
__device__ __half g_mhi[MTOK*DFF];
__device__ __half g_mlo[MTOK*DFF];
// layer weights: fp16 single-precision, N-major [L][N][K]
__device__ __half g_wqkv_h[NLAYER*3*DMODEL*DMODEL];
__device__ __half g_wproj_h[NLAYER*DMODEL*DMODEL];
__device__ __half g_w1_h[NLAYER*DFF*DMODEL];
__device__ __half g_w2_h[NLAYER*DMODEL*DFF];
// lm_head: fp16 hi/lo (3-product for logits accuracy)
__device__ __half g_lmh_hi[VOCAB*DMODEL];
__device__ __half g_lmh_lo[VOCAB*DMODEL];
__device__ float g_tce[MTOK];
__device__ float g_tw [MTOK];
__device__ int   g_mflag;

// ---------------- block reductions ----------------
__device__ __forceinline__ float blockReduceSum(float val) {
    __shared__ float sh[32];
    const int lane = threadIdx.x & 31, wid = threadIdx.x >> 5;
    #pragma unroll
    for (int o = 16; o; o >>= 1) val += __shfl_xor_sync(0xffffffffu, val, o);
    if (lane == 0) sh[wid] = val;
    __syncthreads();
    const int nw = (blockDim.x + 31) >> 5;
    float t = (threadIdx.x < nw) ? sh[threadIdx.x] : 0.0f;
    #pragma unroll
    for (int o = 16; o; o >>= 1) t += __shfl_xor_sync(0xffffffffu, t, o);
    if (threadIdx.x == 0) sh[0] = t;
    __syncthreads();
    t = sh[0];
    __syncthreads();
    return t;
}

__device__ __forceinline__ float blockReduceMax(float val) {
    __shared__ float sh[32];
    const int lane = threadIdx.x & 31, wid = threadIdx.x >> 5;
    #pragma unroll
    for (int o = 16; o; o >>= 1) val = fmaxf(val, __shfl_xor_sync(0xffffffffu, val, o));
    if (lane == 0) sh[wid] = val;
    __syncthreads();
    const int nw = (blockDim.x + 31) >> 5;
    float t = (threadIdx.x < nw) ? sh[threadIdx.x] : -INFINITY;
    #pragma unroll
    for (int o = 16; o; o >>= 1) t = fmaxf(t, __shfl_xor_sync(0xffffffffu, t, o));
    if (threadIdx.x == 0) sh[0] = t;
    __syncthreads();
    t = sh[0];
    __syncthreads();
    return t;
}

// ---------------- helpers ----------------
__device__ __forceinline__ void split_bf16(float a, __nv_bfloat16& hi, __nv_bfloat16& lo) {
    hi = __float2bfloat16(a);
    lo = __float2bfloat16(a - __bfloat162float(hi));
}
__device__ __forceinline__ void split_h(float a, __half& hi, __half& lo) {
    hi = __float2half_rn(a);
    lo = __float2half_rn(a - __half2float(hi));
}
__device__ __forceinline__ uint32_t packbf(__nv_bfloat16 c0, __nv_bfloat16 c1) {
    return (uint32_t)__bfloat16_as_ushort(c0) | ((uint32_t)__bfloat16_as_ushort(c1) << 16);
}

__device__ __forceinline__ void cp16(void* sdst, const void* gsrc) {
    uint32_t sa = (uint32_t)__cvta_generic_to_shared(sdst);
    asm volatile("cp.async.cg.shared.global [%0], [%1], 16;" :: "r"(sa), "l"(gsrc));
}
#define CP_COMMIT() asm volatile("cp.async.commit_group;" ::: "memory")

__device__ __forceinline__ uint32_t smem_u32(const void* p) {
    return (uint32_t)__cvta_generic_to_shared(p);
}

#define SWZ128(off) ((off) ^ (((off) >> 3) & 0x70))

__device__ __forceinline__ void mma16816bf(float* d, const uint32_t* a, const uint32_t* b) {
    asm volatile(
        "mma.sync.aligned.m16n8k16.row.col.f32.bf16.bf16.f32 "
        "{%0,%1,%2,%3}, {%4,%5,%6,%7}, {%8,%9}, {%0,%1,%2,%3};"
        : "+f"(d[0]), "+f"(d[1]), "+f"(d[2]), "+f"(d[3])
        : "r"(a[0]), "r"(a[1]), "r"(a[2]), "r"(a[3]), "r"(b[0]), "r"(b[1]));
}
__device__ __forceinline__ void mma16816h(float* d, const uint32_t* a, const uint32_t* b) {
    asm volatile(
        "mma.sync.aligned.m16n8k16.row.col.f32.f16.f16.f32 "
        "{%0,%1,%2,%3}, {%4,%5,%6,%7}, {%8,%9}, {%0,%1,%2,%3};"
        : "+f"(d[0]), "+f"(d[1]), "+f"(d[2]), "+f"(d[3])
        : "r"(a[0]), "r"(a[1]), "r"(a[2]), "r"(a[3]), "r"(b[0]), "r"(b[1]));
}

__device__ __forceinline__ void ldsm4(uint32_t* r, uint32_t addr) {
    asm volatile("ldmatrix.sync.aligned.m8n8.x4.shared.b16 {%0,%1,%2,%3}, [%4];"
                 : "=r"(r[0]), "=r"(r[1]), "=r"(r[2]), "=r"(r[3]) : "r"(addr));
}

// ---------------- weight pack kernels ----------------
// W [K][N] fp32 -> Wh fp16 [N][K] (tiled transpose)
__global__ __launch_bounds__(256) void convw_h(
    const float* __restrict__ W, __half* __restrict__ Wh, int K, int N)
{
    __shared__ float tile[32][33];
    const int tx = threadIdx.x & 31, ty = threadIdx.x >> 5;
    const int n0 = blockIdx.x * 32, k0 = blockIdx.y * 32;
    const int l = blockIdx.z;
    const float* Wl = W + (size_t)l * K * N;
    #pragma unroll
    for (int i = ty; i < 32; i += 8)
        tile[i][tx] = Wl[(size_t)(k0 + i) * N + n0 + tx];
    __syncthreads();
    __half* Hl = Wh + (size_t)l * N * K;
    #pragma unroll
    for (int i = ty; i < 32; i += 8)
        Hl[(size_t)(n0 + i) * K + k0 + tx] = __float2half_rn(tile[tx][i]);
}

// lm_head split (tok already [V][K])
__global__ __launch_bounds__(256) void convsplit(
    const float* __restrict__ W, __half* __restrict__ hi, __half* __restrict__ lo)
{
    const int i = blockIdx.x * 256 + threadIdx.x;
    __half h, l;
    split_h(W[i], h, l);
    hi[i] = h; lo[i] = l;
}

// ---------------- value_mask dtype probe ----------------
__global__ __launch_bounds__(256) void detect_mask_kernel(const unsigned char* __restrict__ m)
{
    __shared__ int sh[32];
    int s = 0;
    for (int i = threadIdx.x; i < 8192; i += 256)
        if (i & 3) s += m[i];
    #pragma unroll
    for (int o = 16; o; o >>= 1) s += __shfl_xor_sync(0xffffffffu, s, o);
    const int lane = threadIdx.x & 31, wid = threadIdx.x >> 5;
    if (lane == 0) sh[wid] = s;
    __syncthreads();
    if (threadIdx.x < 8) {
        int t = sh[threadIdx.x];
        #pragma unroll
        for (int o = 4; o; o >>= 1) t += __shfl_xor_sync(0xffu, t, o);
        if (threadIdx.x == 0) g_mflag = (t != 0) ? 1 : 0;
    }
}

// ---------------- embed ----------------
__global__ __launch_bounds__(256) void embed_kernel(
    const int* __restrict__ ids, const float* __restrict__ tok,
    const float* __restrict__ pos, float* __restrict__ x)
{
    const int m = blockIdx.x;
    const int t = m & (SEQ - 1);
    const int id = ids[m];
    const float4 a = ((const float4*)(tok + (size_t)id * DMODEL))[threadIdx.x];
    const float4 b = ((const float4*)(pos + (size_t)t  * DMODEL))[threadIdx.x];
    ((float4*)(x + (size_t)m * DMODEL))[threadIdx.x] =
        make_float4(a.x + b.x, a.y + b.y, a.z + b.z, a.w + b.w);
}

// ---------------- layernorm -> split fp16 ----------------
__global__ __launch_bounds__(256) void ln_h_kernel(
    const float* __restrict__ x, const float* __restrict__ w,
    const float* __restrict__ b, __half* __restrict__ yhi,
    __half* __restrict__ ylo)
{
    const int row = blockIdx.x;
    const float4 v = ((const float4*)(x + (size_t)row * DMODEL))[threadIdx.x];
    float s = v.x + v.y + v.z + v.w;
    s = blockReduceSum(s);
    const float mu = s * (1.0f / DMODEL);
    const float d0 = v.x - mu, d1 = v.y - mu, d2 = v.z - mu, d3 = v.w - mu;
    float q = d0*d0 + d1*d1 + d2*d2 + d3*d3;
    q = blockReduceSum(q);
    const float rs = rsqrtf(q * (1.0f / DMODEL) + 1e-5f);
    const float4 w4 = ((const float4*)w)[threadIdx.x];
    const float4 b4 = ((const float4*)b)[threadIdx.x];
    float o0 = d0 * rs * w4.x + b4.x;
    float o1 = d1 * rs * w4.y + b4.y;
    float o2 = d2 * rs * w4.z + b4.z;
    float o3 = d3 * rs * w4.w + b4.w;
    __half h0,l0,h1,l1,h2,l2,h3,l3;
    split_h(o0,h0,l0); split_h(o1,h1,l1); split_h(o2,h2,l2); split_h(o3,h3,l3);
    const size_t base = (size_t)row * DMODEL + threadIdx.x * 4;
    *(__half2*)(yhi + base)     = __halves2half2(h0, h1);
    *(__half2*)(yhi + base + 2) = __halves2half2(h2, h3);
    *(__half2*)(ylo + base)     = __halves2half2(l0, l1);
    *(__half2*)(ylo + base + 2) = __halves2half2(l2, l3);
}

// ---------------- fp16 mma GEMM: CTA 64x64, 8 warps (16x32 tiles), 4 CTAs/SM ----
// C = (Ahi+Alo)[M][K] @ Bh[N][K]^T  (+ Ahi@Blo when THREE), fp32 accum.
enum { EPI_NONE = 0, EPI_RES = 1, EPI_GELU = 2 };

#define GEMM_SMEM_2P (2*24576)   // Ah 8K + Al 8K + Bh 8K per stage = 49152
#define GEMM_SMEM_3P (2*32768)   // + Bl 8K = 65536

template<int EPI, bool THREE>
__global__ __launch_bounds__(256, 4) void gemm_ldsm_kernel(
    const __half* __restrict__ Ahi, const __half* __restrict__ Alo,
    const __half* __restrict__ Bhi, const __half* __restrict__ Blo,
    const float* __restrict__ bias, const float* __restrict__ res,
    float* __restrict__ C, __half* __restrict__ Chi, __half* __restrict__ Clo,
    int M, int N, int K)
{
    constexpr int STB = THREE ? 32768 : 24576;
    extern __shared__ __align__(1024) char smem[];
    const uint32_t sb = smem_u32(smem);
    const int tid = threadIdx.x, lane = tid & 31, wid = tid >> 5;
    const int wm = wid >> 1, wn = wid & 1;              // warp tile (wm*16, wn*32)
    const int bm = blockIdx.y * 64, bn = blockIdx.x * 64;

    float acc[4][4];
    #pragma unroll
    for (int nt = 0; nt < 4; nt++)
        #pragma unroll
        for (int i = 0; i < 4; i++) acc[nt][i] = 0.0f;

    // fill stage s with k-atom kt (64 k elems): A 64 rows, B 64 rows, 128B each
    auto fill = [&](int s, int kt) {
        char* st = smem + s * STB;
        const int k0 = kt << 6;
        #pragma unroll
        for (int i = 0; i < 2; i++) {
            const int idx = tid + i * 256;              // 0..511
            const int row = idx >> 3, c16 = idx & 7;
            const uint32_t sw = SWZ128((uint32_t)((row << 7) + (c16 << 4)));
            const size_t ga = (size_t)(bm + row) * K + k0 + c16 * 8;
            const size_t gb = (size_t)(bn + row) * K + k0 + c16 * 8;
            cp16(st + sw,         Ahi + ga);
            cp16(st + 8192 + sw,  Alo + ga);
            cp16(st + 16384 + sw, Bhi + gb);
            if (THREE) cp16(st + 24576 + sw, Blo + gb);
        }
    };

    const int laneRA = lane & 15;
    const int laneCA = (lane >> 4) << 4;
    const int laneRB = (lane & 7) + ((lane >> 4) << 3);
    const int laneCB = ((lane >> 3) & 1) << 4;

    const int niter = K >> 6;
    fill(0, 0); CP_COMMIT();

    for (int it = 0; it < niter; it++) {
        const int s = it & 1;
        if (it + 1 < niter) {
            fill(s ^ 1, it + 1); CP_COMMIT();
            asm volatile("cp.async.wait_group 1;" ::: "memory");
        } else {
            asm volatile("cp.async.wait_group 0;" ::: "memory");
        }
        __syncthreads();

        const uint32_t aH = sb + s * STB;
        const uint32_t aL = aH + 8192;
        const uint32_t bH = aH + 16384;
        const uint32_t bL = aH + 24576;

        #pragma unroll
        for (int k16 = 0; k16 < 4; k16++) {
            const int kb = k16 * 32;
            uint32_t ah[4], al[4], bh[4][2], bl[4][2];
            {
                const uint32_t off = SWZ128(
                    (uint32_t)(((wm * 16 + laneRA) << 7) + kb + laneCA));
                ldsm4(ah, aH + off);
                ldsm4(al, aL + off);
            }
            #pragma unroll
            for (int j = 0; j < 2; j++) {
                const uint32_t off = SWZ128(
                    (uint32_t)(((wn * 32 + j * 16 + laneRB) << 7) + kb + laneCB));
                ldsm4(&bh[j * 2][0], bH + off);
                if (THREE) ldsm4(&bl[j * 2][0], bL + off);
            }
            #pragma unroll
            for (int nt = 0; nt < 4; nt++) mma16816h(acc[nt], ah, bh[nt]);
            if (THREE) {
                #pragma unroll
                for (int nt = 0; nt < 4; nt++) mma16816h(acc[nt], ah, bl[nt]);
            }
            #pragma unroll
            for (int nt = 0; nt < 4; nt++) mma16816h(acc[nt], al, bh[nt]);
        }
        __syncthreads();
    }

    // ---- epilogue ----
    const int g = lane >> 2, t = lane & 3;
    #pragma unroll
    for (int nt = 0; nt < 4; nt++) {
        const int col = bn + wn * 32 + nt * 8 + 2 * t;
        #pragma unroll
        for (int half = 0; half < 2; half++) {
            const int row = bm + wm * 16 + g + half * 8;
            float v0 = acc[nt][2 * half + 0];
            float v1 = acc[nt][2 * half + 1];
            if (bias) { v0 += bias[col]; v1 += bias[col + 1]; }
            const size_t o = (size_t)row * N + col;
            if (EPI == EPI_GELU) {
                v0 = 0.5f * v0 * (1.0f + erff(v0 * 0.70710678118654752f));
                v1 = 0.5f * v1 * (1.0f + erff(v1 * 0.70710678118654752f));
                __half h0, l0, h1, l1;
                split_h(v0, h0, l0);
                split_h(v1, h1, l1);
                *(__half2*)(Chi + o) = __halves2half2(h0, h1);
                *(__half2*)(Clo + o) = __halves2half2(l0, l1);
            } else {
                if (EPI == EPI_RES) {
                    const float2 r2 = *(const float2*)(res + o);
                    v0 += r2.x; v1 += r2.y;
                }
                *(float2*)(C + o) = make_float2(v0, v1);
            }
        }
    }
}

// ---------------- causal flash attention on tensor cores (R15-validated) ---------
#define ATTN_SMEM_BYTES 65536

__global__ __launch_bounds__(128) void attn_mma_kernel(
    const float* __restrict__ qkv,
    __half* __restrict__ ohi, __half* __restrict__ olo)
{
    extern __shared__ __align__(1024) char asmem[];
    char* Qh = asmem;                 // 128 x 128B
    char* Ql = asmem + 16384;
    char* Kh = asmem + 32768;         // 64 x 128B
    char* Kl = asmem + 40960;
    char* Vh = asmem + 49152;         // Vt[d][key] 64 x 128B
    char* Vl = asmem + 57344;
    const uint32_t uQh = smem_u32(Qh), uQl = smem_u32(Ql);
    const uint32_t uKh = smem_u32(Kh), uKl = smem_u32(Kl);
    const uint32_t uVh = smem_u32(Vh), uVl = smem_u32(Vl);

    const int qt = blockIdx.x, h = blockIdx.y, b = blockIdx.z;
    const int tid = threadIdx.x, lane = tid & 31, w = tid >> 5;
    const int g = lane >> 2, t = lane & 3;
    const int qBase = qt * 128;

    const float* qpB = qkv + (size_t)b * SEQ * (3 * DMODEL) + h * HEADDIM;
    const float* kpB = qpB + DMODEL;
    const float* vpB = qpB + 2 * DMODEL;

    {
        const float* qrow = qpB + (size_t)(qBase + tid) * (3 * DMODEL);
        #pragma unroll
        for (int i = 0; i < 16; i++) {
            const float4 v = *(const float4*)(qrow + 4 * i);
            __nv_bfloat16 h0,l0,h1,l1,h2,l2,h3,l3;
            split_bf16(v.x,h0,l0); split_bf16(v.y,h1,l1);
            split_bf16(v.z,h2,l2); split_bf16(v.w,h3,l3);
            const uint32_t sw = SWZ128((uint32_t)(tid * 128 + i * 8));
            *(uint32_t*)(Qh + sw)     = packbf(h0, h1);
            *(uint32_t*)(Qh + sw + 4) = packbf(h2, h3);
            *(uint32_t*)(Ql + sw)     = packbf(l0, l1);
            *(uint32_t*)(Ql + sw + 4) = packbf(l2, l3);
        }
    }

    float m_s[4], l_s[4];
    #pragma unroll
    for (int r = 0; r < 4; r++) { m_s[r] = -INFINITY; l_s[r] = 0.0f; }
    float acc_o[2][8][4];
    #pragma unroll
    for (int mt = 0; mt < 2; mt++)
        #pragma unroll
        for (int j = 0; j < 8; j++)
            #pragma unroll
            for (int i = 0; i < 4; i++) acc_o[mt][j][i] = 0.0f;

    const int laneRA = lane & 15;
    const int laneCA = (lane >> 4) << 4;
    const int laneRB = (lane & 7) + ((lane >> 4) << 3);
    const int laneCB = ((lane >> 3) & 1) << 4;

    const int nkt = 2 * qt + 2;
    for (int kt = 0; kt < nkt; kt++) {
        __syncthreads();
        {
            const int key = tid >> 1, hf = tid & 1;
            const float* krow = kpB + (size_t)(kt * 64 + key) * (3 * DMODEL) + hf * 32;
            const float* vrow = vpB + (size_t)(kt * 64 + key) * (3 * DMODEL) + hf * 32;
            #pragma unroll
            for (int i = 0; i < 8; i++) {
                const int d = hf * 32 + 4 * i;
                const float4 kv = *(const float4*)(krow + 4 * i);
                __nv_bfloat16 h0,l0,h1,l1,h2,l2,h3,l3;
                split_bf16(kv.x,h0,l0); split_bf16(kv.y,h1,l1);
                split_bf16(kv.z,h2,l2); split_bf16(kv.w,h3,l3);
                const uint32_t sw = SWZ128((uint32_t)(key * 128 + d * 2));
                *(uint32_t*)(Kh + sw)     = packbf(h0, h1);
                *(uint32_t*)(Kh + sw + 4) = packbf(h2, h3);
                *(uint32_t*)(Kl + sw)     = packbf(l0, l1);
                *(uint32_t*)(Kl + sw + 4) = packbf(l2, l3);

                const float4 vv = *(const float4*)(vrow + 4 * i);
                const float vf[4] = {vv.x, vv.y, vv.z, vv.w};
                #pragma unroll
                for (int c = 0; c < 4; c++) {
                    __nv_bfloat16 vh_, vl_;
                    split_bf16(vf[c], vh_, vl_);
                    const uint32_t swv = SWZ128((uint32_t)((d + c) * 128 + key * 2));
                    *(__nv_bfloat16*)(Vh + swv) = vh_;
                    *(__nv_bfloat16*)(Vl + swv) = vl_;
                }
            }
        }
        __syncthreads();

        float s[2][8][4];
        #pragma unroll
        for (int mt = 0; mt < 2; mt++)
            #pragma unroll
            for (int j = 0; j < 8; j++)
                #pragma unroll
                for (int i = 0; i < 4; i++) s[mt][j][i] = 0.0f;

        #pragma unroll
        for (int kk = 0; kk < 4; kk++) {
            const int kb = kk * 32;
            uint32_t qh[2][4], ql[2][4], kh[8][2], kl[8][2];
            #pragma unroll
            for (int mt = 0; mt < 2; mt++) {
                const uint32_t off = SWZ128(
                    (uint32_t)(((w * 32 + mt * 16 + laneRA) << 7) + kb + laneCA));
                ldsm4(qh[mt], uQh + off);
                ldsm4(ql[mt], uQl + off);
            }
            #pragma unroll
            for (int j = 0; j < 4; j++) {
                const uint32_t off = SWZ128(
                    (uint32_t)(((j * 16 + laneRB) << 7) + kb + laneCB));
                ldsm4(&kh[j * 2][0], uKh + off);
                ldsm4(&kl[j * 2][0], uKl + off);
            }
            #pragma unroll
            for (int mt = 0; mt < 2; mt++)
                #pragma unroll
                for (int n = 0; n < 8; n++) mma16816bf(s[mt][n], qh[mt], kh[n]);
            #pragma unroll
            for (int mt = 0; mt < 2; mt++)
                #pragma unroll
                for (int n = 0; n < 8; n++) mma16816bf(s[mt][n], qh[mt], kl[n]);
            #pragma unroll
            for (int mt = 0; mt < 2; mt++)
                #pragma unroll
                for (int n = 0; n < 8; n++) mma16816bf(s[mt][n], ql[mt], kh[n]);
        }

        const int k0g = kt * 64;
        #pragma unroll
        for (int mt = 0; mt < 2; mt++) {
            #pragma unroll
            for (int half = 0; half < 2; half++) {
                const int qrow = qBase + w * 32 + mt * 16 + g + half * 8;
                const int r = mt * 2 + half;
                float tmax = -INFINITY;
                #pragma unroll
                for (int j = 0; j < 8; j++) {
                    const int key = k0g + j * 8 + 2 * t;
                    float v0 = s[mt][j][2 * half]     * 0.125f;
                    float v1 = s[mt][j][2 * half + 1] * 0.125f;
                    v0 = (key     <= qrow) ? v0 : -INFINITY;
                    v1 = (key + 1 <= qrow) ? v1 : -INFINITY;
                    s[mt][j][2 * half]     = v0;
                    s[mt][j][2 * half + 1] = v1;
                    tmax = fmaxf(tmax, fmaxf(v0, v1));
                }
                tmax = fmaxf(tmax, __shfl_xor_sync(0xffffffffu, tmax, 1));
                tmax = fmaxf(tmax, __shfl_xor_sync(0xffffffffu, tmax, 2));
                const float mnew = fmaxf(m_s[r], tmax);
                const float corr = __expf(m_s[r] - mnew);
                float lsum = 0.0f;
                #pragma unroll
                for (int j = 0; j < 8; j++) {
                    const float e0 = __expf(s[mt][j][2 * half]     - mnew);
                    const float e1 = __expf(s[mt][j][2 * half + 1] - mnew);
                    s[mt][j][2 * half]     = e0;
                    s[mt][j][2 * half + 1] = e1;
                    lsum += e0 + e1;
                }
                lsum += __shfl_xor_sync(0xffffffffu, lsum, 1);
                lsum += __shfl_xor_sync(0xffffffffu, lsum, 2);
                l_s[r] = l_s[r] * corr + lsum;
                m_s[r] = mnew;
                #pragma unroll
                for (int j = 0; j < 8; j++) {
                    acc_o[mt][j][2 * half]     *= corr;
                    acc_o[mt][j][2 * half + 1] *= corr;
                }
            }
        }

        #pragma unroll
        for (int kk = 0; kk < 4; kk++) {
            uint32_t aPh[2][4], aPl[2][4];
            #pragma unroll
            for (int mt = 0; mt < 2; mt++) {
                #pragma unroll
                for (int half2 = 0; half2 < 2; half2++) {
                    const int j = 2 * kk + half2;
                    __nv_bfloat16 h0,l0,h1,l1,h2,l2,h3,l3;
                    split_bf16(s[mt][j][0], h0, l0);
                    split_bf16(s[mt][j][1], h1, l1);
                    split_bf16(s[mt][j][2], h2, l2);
                    split_bf16(s[mt][j][3], h3, l3);
                    aPh[mt][2 * half2]     = packbf(h0, h1);
                    aPh[mt][2 * half2 + 1] = packbf(h2, h3);
                    aPl[mt][2 * half2]     = packbf(l0, l1);
                    aPl[mt][2 * half2 + 1] = packbf(l2, l3);
                }
            }
            uint32_t vh[8][2], vl[8][2];
            #pragma unroll
            for (int j = 0; j < 4; j++) {
                const uint32_t off = SWZ128(
                    (uint32_t)(((j * 16 + laneRB) << 7) + kk * 32 + laneCB));
                ldsm4(&vh[j * 2][0], uVh + off);
                ldsm4(&vl[j * 2][0], uVl + off);
            }
            #pragma unroll
            for (int mt = 0; mt < 2; mt++)
                #pragma unroll
                for (int n = 0; n < 8; n++) mma16816bf(acc_o[mt][n], aPh[mt], vh[n]);
            #pragma unroll
            for (int mt = 0; mt < 2; mt++)
                #pragma unroll
                for (int n = 0; n < 8; n++) mma16816bf(acc_o[mt][n], aPh[mt], vl[n]);
            #pragma unroll
            for (int mt = 0; mt < 2; mt++)
                #pragma unroll
                for (int n = 0; n < 8; n++) mma16816bf(acc_o[mt][n], aPl[mt], vh[n]);
        }
    }

    #pragma unroll
    for (int mt = 0; mt < 2; mt++) {
        #pragma unroll
        for (int half = 0; half < 2; half++) {
            const int qrow = qBase + w * 32 + mt * 16 + g + half * 8;
            const float inv = 1.0f / l_s[mt * 2 + half];
            const size_t obase = ((size_t)b * SEQ + qrow) * DMODEL + h * HEADDIM;
            #pragma unroll
            for (int j = 0; j < 8; j++) {
                const float v0 = acc_o[mt][j][2 * half]     * inv;
                const float v1 = acc_o[mt][j][2 * half + 1] * inv;
                __half h0, l0, h1, l1;
                split_h(v0, h0, l0);
                split_h(v1, h1, l1);
                const size_t o = obase + j * 8 + 2 * t;
                *(__half2*)(ohi + o) = __halves2half2(h0, h1);
                *(__half2*)(olo + o) = __halves2half2(l0, l1);
            }
        }
    }
}

// ---------------- loss ----------------
__global__ __launch_bounds__(256) void loss_token_kernel(
    const float* __restrict__ logits, const int* __restrict__ targets,
    const void* __restrict__ vmask,
    float* __restrict__ tce, float* __restrict__ tw)
{
    const int row = blockIdx.x;
    const float* lr = logits + (size_t)row * VOCAB;
    float v[16];
    #pragma unroll
    for (int i = 0; i < 16; i++) v[i] = lr[threadIdx.x + 256 * i];
    float mx = v[0];
    #pragma unroll
    for (int i = 1; i < 16; i++) mx = fmaxf(mx, v[i]);
    mx = blockReduceMax(mx);
    float se = 0.0f;
    #pragma unroll
    for (int i = 0; i < 16; i++) se += __expf(v[i] - mx);
    se = blockReduceSum(se);
    if (threadIdx.x == 0) {
        const int tgt = targets[row];
        const float lse = mx + logf(se);
        const float nll = lse - lr[tgt];
        int mv;
        if (g_mflag) mv = ((const unsigned char*)vmask)[row];
        else         mv = ((const int*)vmask)[row];
        const float w = 1.0f + 4.0f * ((mv != 0) ? 1.0f : 0.0f);
        tce[row] = (tgt == 0) ? 0.0f : nll * w;
        tw[row]  = w;
    }
}

__global__ __launch_bounds__(256) void loss_final_kernel(
    const float* __restrict__ tce, const float* __restrict__ tw, float* __restrict__ out)
{
    float a = 0.0f, b = 0.0f;
    for (int i = threadIdx.x; i < MTOK; i += 256) { a += tce[i]; b += tw[i]; }
    a = blockReduceSum(a);
    b = blockReduceSum(b);
    if (threadIdx.x == 0) out[0] = a / b;
}

// ---------------- host driver ----------------
extern "C" void kernel_launch(void* const* d_in, const int* in_sizes, int n_in,
                              void* d_out, int out_size)
{
    (void)in_sizes; (void)n_in;
    const int*   ids   = (const int*)d_in[0];
    const int*   tgts  = (const int*)d_in[1];
    const void*  vmask = (const void*)d_in[2];
    const float* tok   = (const float*)d_in[3];
    const float* pos   = (const float*)d_in[4];
    const float* ln1w  = (const float*)d_in[5];
    const float* ln1b  = (const float*)d_in[6];
    const float* wqkv  = (const float*)d_in[7];
    const float* bqkv  = (const float*)d_in[8];
    const float* wproj = (const float*)d_in[9];
    const float* bproj = (const float*)d_in[10];
    const float* ln2w  = (const float*)d_in[11];
    const float* ln2b  = (const float*)d_in[12];
    const float* w1    = (const float*)d_in[13];
    const float* b1    = (const float*)d_in[14];
    const float* w2    = (const float*)d_in[15];
    const float* b2    = (const float*)d_in[16];
    const float* lnfw  = (const float*)d_in[17];
    const float* lnfb  = (const float*)d_in[18];
    float* out = (float*)d_out;

    float *x, *qkv, *tce, *tw;
    __half *hhi, *hlo, *mhi, *mlo;
    __half *wq_h, *wp_h, *w1_h, *w2_h, *lm_hi, *lm_lo;
    cudaGetSymbolAddress((void**)&x,    g_x);
    cudaGetSymbolAddress((void**)&qkv,  g_qkv);
    cudaGetSymbolAddress((void**)&hhi,  g_hhi);
    cudaGetSymbolAddress((void**)&hlo,  g_hlo);
    cudaGetSymbolAddress((void**)&mhi,  g_mhi);
    cudaGetSymbolAddress((void**)&mlo,  g_mlo);
    cudaGetSymbolAddress((void**)&wq_h, g_wqkv_h);
    cudaGetSymbolAddress((void**)&wp_h, g_wproj_h);
    cudaGetSymbolAddress((void**)&w1_h, g_w1_h);
    cudaGetSymbolAddress((void**)&w2_h, g_w2_h);
    cudaGetSymbolAddress((void**)&lm_hi, g_lmh_hi);
    cudaGetSymbolAddress((void**)&lm_lo, g_lmh_lo);
    cudaGetSymbolAddress((void**)&tce,  g_tce);
    cudaGetSymbolAddress((void**)&tw,   g_tw);

    cudaFuncSetAttribute(gemm_ldsm_kernel<EPI_NONE, false>,
                         cudaFuncAttributeMaxDynamicSharedMemorySize, GEMM_SMEM_2P);
    cudaFuncSetAttribute(gemm_ldsm_kernel<EPI_RES, false>,
                         cudaFuncAttributeMaxDynamicSharedMemorySize, GEMM_SMEM_2P);
    cudaFuncSetAttribute(gemm_ldsm_kernel<EPI_GELU, false>,
                         cudaFuncAttributeMaxDynamicSharedMemorySize, GEMM_SMEM_2P);
    cudaFuncSetAttribute(gemm_ldsm_kernel<EPI_NONE, true>,
                         cudaFuncAttributeMaxDynamicSharedMemorySize, GEMM_SMEM_3P);
    cudaFuncSetAttribute(attn_mma_kernel,
                         cudaFuncAttributeMaxDynamicSharedMemorySize, ATTN_SMEM_BYTES);

    // ---- pack weights: [K][N] fp32 -> [N][K] fp16 ----
    convw_h<<<dim3(3*DMODEL/32, DMODEL/32, NLAYER), 256>>>(wqkv,  wq_h, DMODEL, 3*DMODEL);
    convw_h<<<dim3(DMODEL/32,   DMODEL/32, NLAYER), 256>>>(wproj, wp_h, DMODEL, DMODEL);
    convw_h<<<dim3(DFF/32,      DMODEL/32, NLAYER), 256>>>(w1,    w1_h, DMODEL, DFF);
    convw_h<<<dim3(DMODEL/32,   DFF/32,    NLAYER), 256>>>(w2,    w2_h, DFF,    DMODEL);
    convsplit<<<VOCAB*DMODEL/256, 256>>>(tok, lm_hi, lm_lo);

    detect_mask_kernel<<<1, 256>>>((const unsigned char*)vmask);
    embed_kernel<<<MTOK, 256>>>(ids, tok, pos, x);

    const size_t wq_s = (size_t)3*DMODEL*DMODEL;
    const size_t wp_s = (size_t)DMODEL*DMODEL;
    const size_t w1_s = (size_t)DFF*DMODEL;
    const size_t w2_s = (size_t)DMODEL*DFF;

    for (int l = 0; l < NLAYER; l++) {
        ln_h_kernel<<<MTOK, 256>>>(x, ln1w + l*DMODEL, ln1b + l*DMODEL, hhi, hlo);

        gemm_ldsm_kernel<EPI_NONE, false><<<dim3(3*DMODEL/64, MTOK/64), 256, GEMM_SMEM_2P>>>(
            hhi, hlo, wq_h + l*wq_s, nullptr,
            bqkv + (size_t)l*3*DMODEL, nullptr, qkv, nullptr, nullptr,
            MTOK, 3*DMODEL, DMODEL);

        attn_mma_kernel<<<dim3(SEQ/128, NHEAD, BATCH), 128, ATTN_SMEM_BYTES>>>(qkv, hhi, hlo);

        gemm_ldsm_kernel<EPI_RES, false><<<dim3(DMODEL/64, MTOK/64), 256, GEMM_SMEM_2P>>>(
            hhi, hlo, wp_h + l*wp_s, nullptr,
            bproj + (size_t)l*DMODEL, x, x, nullptr, nullptr,
            MTOK, DMODEL, DMODEL);

        ln_h_kernel<<<MTOK, 256>>>(x, ln2w + l*DMODEL, ln2b + l*DMODEL, hhi, hlo);

        gemm_ldsm_kernel<EPI_GELU, false><<<dim3(DFF/64, MTOK/64), 256, GEMM_SMEM_2P>>>(
            hhi, hlo, w1_h + l*w1_s, nullptr,
            b1 + (size_t)l*DFF, nullptr, nullptr, mhi, mlo,
            MTOK, DFF, DMODEL);

        gemm_ldsm_kernel<EPI_RES, false><<<dim3(DMODEL/64, MTOK/64), 256, GEMM_SMEM_2P>>>(
            mhi, mlo, w2_h + l*w2_s, nullptr,
            b2 + (size_t)l*DMODEL, x, x, nullptr, nullptr,
            MTOK, DMODEL, DFF);
    }

    ln_h_kernel<<<MTOK, 256>>>(x, lnfw, lnfb, hhi, hlo);

    // lm_head: 3-product fp16 (logits accuracy)
    gemm_ldsm_kernel<EPI_NONE, true><<<dim3(VOCAB/64, MTOK/64), 256, GEMM_SMEM_3P>>>(
        hhi, hlo, lm_hi, lm_lo, nullptr, nullptr, out, nullptr, nullptr,
        MTOK, VOCAB, DMODEL);

    if (out_size > MTOK * VOCAB) {
        loss_token_kernel<<<MTOK, 256>>>(out, tgts, vmask, tce, tw);
        loss_final_kernel<<<1, 256>>>(tce, tw, out + (size_t)MTOK * VOCAB);
    }
}